// round 6
// baseline (speedup 1.0000x reference)
#include <cuda_runtime.h>

// HWnet: B scalar queries vs sorted anchor grid, 9-pt softmax window gather.
//
// R5: counting-sort by window base + register-level row reuse.
//  K0: zero histogram.
//  K1: per-query nearest idx + normalized weights -> scratch; REDG histogram.
//  K2: single-block exclusive scan of 2048 bins -> cursors.
//  K3: scatter qids into base-sorted order.
//  K4: half-warp walks a run of 8 base-sorted queries; 9 window rows held in
//      registers, reloaded only on base change (~1x per run in the bulk).
//      FMA-bound instead of L1-replay-bound.

#define B_Q   131072
#define T_T   2048
#define D_D   64
#define E_E   4
#define W_W   9
#define RUN   8          // sorted queries per half-warp in K4
#define NBIN  2048

__device__ float4 g_wscratch[(size_t)B_Q * 3];
__device__ int    g_hist[NBIN];
__device__ int    g_cursor[NBIN];
__device__ int    g_sorted[B_Q];

// ---------------------------------------------------------------- K0: zero
__global__ void k0_zero_hist()
{
    int t = blockIdx.x * blockDim.x + threadIdx.x;
    if (t < NBIN) g_hist[t] = 0;
}

// --------------------------------------------------- K1: weights + histogram
__global__ __launch_bounds__(256) void k1_weights(
    const float* __restrict__ x,
    const float* __restrict__ ev,
    const float* __restrict__ tc,
    const int*   __restrict__ idx_tab,
    int nq)
{
    int q = blockIdx.x * blockDim.x + threadIdx.x;
    if (q >= nq) return;

    float xv = __ldg(&x[q]);

    // Uniform-grid guess (ev is linspace), exact +-2 argmin refine with
    // strict-< first-index tie-break (matches reference argmin).
    float e0 = __ldg(&ev[0]);
    float eN = __ldg(&ev[T_T - 1]);
    float inv_step = (float)(T_T - 1) / (eN - e0);
    int g = __float2int_rn((xv - e0) * inv_step);
    g = min(max(g, 0), T_T - 1);

    int lo = max(g - 2, 0), hi = min(g + 2, T_T - 1);
    int nidx = lo;
    float bd = 3.402823466e+38f;
    for (int j = lo; j <= hi; ++j) {
        float d = xv - __ldg(&ev[j]);
        d = d * d;
        if (d < bd) { bd = d; nidx = j; }
    }

    // takecare uses UNCLAMPED nearest idx; window uses clamped.
    float take = __ldg(&tc[nidx]);
    int idx_c = min(max(nidx, E_E), T_T - 1 - E_E);

    float lg[W_W];
    float m = -3.402823466e+38f;
    #pragma unroll
    for (int j = 0; j < W_W; ++j) {
        int w = idx_c + __ldg(&idx_tab[j]);
        float d = xv - __ldg(&ev[w]);
        float l = -(d * d) * take;
        lg[j] = l;
        m = fmaxf(m, l);
    }
    float ssum = 0.0f;
    #pragma unroll
    for (int j = 0; j < W_W; ++j) {
        float e = __expf(lg[j] - m);
        lg[j] = e;
        ssum += e;
    }
    float inv = __frcp_rn(ssum);

    g_wscratch[(size_t)q * 3 + 0] =
        make_float4(lg[0] * inv, lg[1] * inv, lg[2] * inv, lg[3] * inv);
    g_wscratch[(size_t)q * 3 + 1] =
        make_float4(lg[4] * inv, lg[5] * inv, lg[6] * inv, lg[7] * inv);
    g_wscratch[(size_t)q * 3 + 2] =
        make_float4(lg[8] * inv, __int_as_float(idx_c), 0.f, 0.f);

    atomicAdd(&g_hist[idx_c], 1);   // no return use -> REDG
}

// --------------------------------------------- K2: exclusive scan (1 block)
__global__ __launch_bounds__(256) void k2_scan()
{
    __shared__ int s_warp[8];
    int t = threadIdx.x;

    int v[8];
    int run = 0;
    #pragma unroll
    for (int j = 0; j < 8; ++j) {
        int tmp = g_hist[t * 8 + j];
        v[j] = run;                 // thread-local exclusive prefix
        run += tmp;
    }

    // warp inclusive scan of run
    int lane = t & 31, w = t >> 5;
    int xi = run;
    #pragma unroll
    for (int d = 1; d < 32; d <<= 1) {
        int y = __shfl_up_sync(0xffffffffu, xi, d);
        if (lane >= d) xi += y;
    }
    if (lane == 31) s_warp[w] = xi;
    __syncthreads();
    if (t == 0) {
        int acc = 0;
        #pragma unroll
        for (int k = 0; k < 8; ++k) { int tmp = s_warp[k]; s_warp[k] = acc; acc += tmp; }
    }
    __syncthreads();

    int thread_excl = (xi - run) + s_warp[w];
    #pragma unroll
    for (int j = 0; j < 8; ++j)
        g_cursor[t * 8 + j] = thread_excl + v[j];
}

// ------------------------------------------------------------- K3: scatter
__global__ __launch_bounds__(256) void k3_scatter(int nq)
{
    int q = blockIdx.x * blockDim.x + threadIdx.x;
    if (q >= nq) return;
    float4 w2 = __ldg(&g_wscratch[(size_t)q * 3 + 2]);
    int base = __float_as_int(w2.y);
    int pos = atomicAdd(&g_cursor[base], 1);
    g_sorted[pos] = q;
}

// ------------------------------------------- K4: gather with register reuse
__global__ __launch_bounds__(256) void k4_compute(
    const float* __restrict__ vec,
    float*       __restrict__ out,
    int nq)
{
    int gt = blockIdx.x * blockDim.x + threadIdx.x;
    int h = gt >> 4;          // half-warp id -> one run of RUN sorted queries
    int c = gt & 15;          // float4 chunk of D (fixed per thread)
    int start = h * RUN;
    if (start >= nq) return;

    int cur = -1;
    float4 r0, r1, r2, r3, r4, r5, r6, r7, r8;
    r0 = r1 = r2 = r3 = r4 = r5 = r6 = r7 = r8 = make_float4(0.f, 0.f, 0.f, 0.f);

    #pragma unroll
    for (int i = 0; i < RUN; ++i) {
        int pos = start + i;
        if (pos >= nq) break;
        int qid = __ldg(&g_sorted[pos]);

        float4 w03 = __ldg(&g_wscratch[(size_t)qid * 3 + 0]);
        float4 w47 = __ldg(&g_wscratch[(size_t)qid * 3 + 1]);
        float4 w8b = __ldg(&g_wscratch[(size_t)qid * 3 + 2]);
        int base = __float_as_int(w8b.y);

        if (base != cur) {
            cur = base;
            const float4* vp =
                reinterpret_cast<const float4*>(vec + (size_t)(base - E_E) * D_D) + c;
            r0 = __ldg(vp + 0 * (D_D / 4));
            r1 = __ldg(vp + 1 * (D_D / 4));
            r2 = __ldg(vp + 2 * (D_D / 4));
            r3 = __ldg(vp + 3 * (D_D / 4));
            r4 = __ldg(vp + 4 * (D_D / 4));
            r5 = __ldg(vp + 5 * (D_D / 4));
            r6 = __ldg(vp + 6 * (D_D / 4));
            r7 = __ldg(vp + 7 * (D_D / 4));
            r8 = __ldg(vp + 8 * (D_D / 4));
        }

        float4 a, b;
        a.x = w03.x * r0.x;            a.y = w03.x * r0.y;
        a.z = w03.x * r0.z;            a.w = w03.x * r0.w;
        b.x = w03.y * r1.x;            b.y = w03.y * r1.y;
        b.z = w03.y * r1.z;            b.w = w03.y * r1.w;
        a.x = fmaf(w03.z, r2.x, a.x);  a.y = fmaf(w03.z, r2.y, a.y);
        a.z = fmaf(w03.z, r2.z, a.z);  a.w = fmaf(w03.z, r2.w, a.w);
        b.x = fmaf(w03.w, r3.x, b.x);  b.y = fmaf(w03.w, r3.y, b.y);
        b.z = fmaf(w03.w, r3.z, b.z);  b.w = fmaf(w03.w, r3.w, b.w);
        a.x = fmaf(w47.x, r4.x, a.x);  a.y = fmaf(w47.x, r4.y, a.y);
        a.z = fmaf(w47.x, r4.z, a.z);  a.w = fmaf(w47.x, r4.w, a.w);
        b.x = fmaf(w47.y, r5.x, b.x);  b.y = fmaf(w47.y, r5.y, b.y);
        b.z = fmaf(w47.y, r5.z, b.z);  b.w = fmaf(w47.y, r5.w, b.w);
        a.x = fmaf(w47.z, r6.x, a.x);  a.y = fmaf(w47.z, r6.y, a.y);
        a.z = fmaf(w47.z, r6.z, a.z);  a.w = fmaf(w47.z, r6.w, a.w);
        b.x = fmaf(w47.w, r7.x, b.x);  b.y = fmaf(w47.w, r7.y, b.y);
        b.z = fmaf(w47.w, r7.z, b.z);  b.w = fmaf(w47.w, r7.w, b.w);
        a.x = fmaf(w8b.x, r8.x, a.x);  a.y = fmaf(w8b.x, r8.y, a.y);
        a.z = fmaf(w8b.x, r8.z, a.z);  a.w = fmaf(w8b.x, r8.w, a.w);

        float4 acc = make_float4(a.x + b.x, a.y + b.y, a.z + b.z, a.w + b.w);
        reinterpret_cast<float4*>(out)[(size_t)qid * 16 + c] = acc;
    }
}

extern "C" void kernel_launch(void* const* d_in, const int* in_sizes, int n_in,
                              void* d_out, int out_size)
{
    const float* x    = (const float*)d_in[0];
    const float* ev   = (const float*)d_in[1];
    const float* tc   = (const float*)d_in[2];
    const float* vec  = (const float*)d_in[3];
    const int*   itab = (const int*)d_in[4];
    float* out = (float*)d_out;

    int nq = in_sizes[0];

    k0_zero_hist<<<(NBIN + 255) / 256, 256>>>();
    k1_weights<<<(nq + 255) / 256, 256>>>(x, ev, tc, itab, nq);
    k2_scan<<<1, 256>>>();
    k3_scatter<<<(nq + 255) / 256, 256>>>(nq);

    int halfwarps = (nq + RUN - 1) / RUN;
    int threads = halfwarps * 16;
    k4_compute<<<(threads + 255) / 256, 256>>>(vec, out, nq);
}

// round 7
// speedup vs baseline: 1.1973x; 1.1973x over previous
#include <cuda_runtime.h>

// HWnet: B scalar queries vs sorted anchor grid (linspace), 9-pt softmax
// window over vector_table[T=2048, D=64].
//
// R6: fused warp-per-query kernel.
//  - Scalar part (nearest idx via uniform-grid guess + exact +-2 argmin
//    refine, softmax over the 9-point window) computed warp-parallel with
//    shuffles: lanes 0..4 hold argmin candidates, lanes 0..8 hold logits.
//  - Gather part: the 9 window rows are one contiguous 2304 B span = 18
//    128B-aligned lines. 18x LDG.32 with contiguous lanes -> every load is
//    exactly ONE L1 line (1 wavefront, no within-LDG replays), vs 4-line
//    LDG.128 footprints before (~2.07 cyc/wf replay regime).
//  - Lane l owns output cols l and 32+l; 2 coalesced 1-line STG.32.

#define T_T   2048
#define D_D   64
#define E_E   4
#define W_W   9
#define FULL  0xffffffffu

__global__ __launch_bounds__(256) void hwnet_fused(
    const float* __restrict__ x,
    const float* __restrict__ ev,
    const float* __restrict__ tc,
    const float* __restrict__ vec,
    const int*   __restrict__ idx_tab,
    float*       __restrict__ out,
    int nq)
{
    const int lane = threadIdx.x & 31;
    const int q = blockIdx.x * 8 + (threadIdx.x >> 5);
    if (q >= nq) return;

    const float xv = __ldg(&x[q]);

    // ---- nearest-anchor index: uniform-grid guess + exact +-2 refine ----
    const float e0 = __ldg(&ev[0]);
    const float eN = __ldg(&ev[T_T - 1]);
    const float inv_step = (float)(T_T - 1) / (eN - e0);
    int g = __float2int_rn((xv - e0) * inv_step);
    g = min(max(g, 0), T_T - 1);

    // Lanes 0..4 evaluate candidates g-2..g+2 (clamped); argmin with
    // first-index tie-break (strict <, then smaller index) via butterfly.
    int cand = min(max(g - 2 + lane, 0), T_T - 1);
    float dmin = 3.402823466e+38f;
    if (lane < 5) {
        float e = __ldg(&ev[cand]);
        dmin = (xv - e) * (xv - e);
    }
    int bidx = cand;
    #pragma unroll
    for (int off = 4; off >= 1; off >>= 1) {
        float d2 = __shfl_xor_sync(FULL, dmin, off);
        int   i2 = __shfl_xor_sync(FULL, bidx, off);
        if (d2 < dmin || (d2 == dmin && i2 < bidx)) { dmin = d2; bidx = i2; }
    }
    const int nidx = __shfl_sync(FULL, bidx, 0);

    // takecare uses UNCLAMPED nearest idx; window uses clamped.
    const float take = __ldg(&tc[nidx]);
    const int idx_c = min(max(nidx, E_E), T_T - 1 - E_E);

    // ---- softmax over 9-point window, lanes 0..8 ----
    float lg = -3.402823466e+38f;
    if (lane < W_W) {
        int w = idx_c + __ldg(&idx_tab[lane]);
        float d = xv - __ldg(&ev[w]);
        lg = -(d * d) * take;
    }
    float m = lg;
    #pragma unroll
    for (int off = 8; off >= 1; off >>= 1)
        m = fmaxf(m, __shfl_xor_sync(FULL, m, off));   // max over 16-lane group

    float eexp = 0.0f;
    if (lane < W_W) eexp = __expf(lg - m);
    float ssum = eexp;
    #pragma unroll
    for (int off = 8; off >= 1; off >>= 1)
        ssum += __shfl_xor_sync(FULL, ssum, off);      // sum over 16-lane group
    const float myw = eexp * __frcp_rn(ssum);

    // Broadcast the 9 normalized weights to all lanes.
    float wreg[W_W];
    #pragma unroll
    for (int j = 0; j < W_W; ++j)
        wreg[j] = __shfl_sync(FULL, myw, j);

    // ---- gather: contiguous 576-float span, 18 one-line LDG.32 ----
    // element e = k*32 + lane -> row j = k>>1, col = (k&1)*32 + lane.
    const float* wp = vec + (size_t)(idx_c - E_E) * D_D;
    float acc0 = 0.0f, acc1 = 0.0f;
    #pragma unroll
    for (int k = 0; k < 18; ++k) {
        float v = __ldg(wp + k * 32 + lane);
        float wt = wreg[k >> 1];
        if (k & 1) acc1 = fmaf(wt, v, acc1);
        else       acc0 = fmaf(wt, v, acc0);
    }

    float* op = out + (size_t)q * D_D;
    op[lane]      = acc0;
    op[32 + lane] = acc1;
}

extern "C" void kernel_launch(void* const* d_in, const int* in_sizes, int n_in,
                              void* d_out, int out_size)
{
    const float* x    = (const float*)d_in[0];
    const float* ev   = (const float*)d_in[1];
    const float* tc   = (const float*)d_in[2];
    const float* vec  = (const float*)d_in[3];
    const int*   itab = (const int*)d_in[4];
    float* out = (float*)d_out;

    int nq = in_sizes[0];
    int grid = (nq + 7) / 8;          // 8 warps (queries) per 256-thread block
    hwnet_fused<<<grid, 256>>>(x, ev, tc, vec, itab, out, nq);
}

// round 9
// speedup vs baseline: 1.6749x; 1.3988x over previous
#include <cuda_runtime.h>

// HWnet: B scalar queries vs sorted anchor grid (linspace), 9-pt softmax
// window over vector_table[T=2048, D=64].
//
// R7 = R4's two-kernel split + R6's one-line-per-load gather:
//  K1: one thread per query -> nearest idx + 9 normalized weights.
//      SoA scratch (3 float4 arrays) for coalesced stores.
//  K2: one WARP per query, zero shuffles:
//      3 uniform 1-line LDG.128 (weights) + 18 one-line LDG.32 over the
//      contiguous 2304B window span + 18 FMA + 2 one-line STG.32.
//      Every memory instruction touches exactly one L1 line -> no
//      within-LDG replays (the 2.07 cyc/wf regime that bounded R4).

#define B_Q   131072
#define T_T   2048
#define D_D   64
#define E_E   4
#define W_W   9

__device__ float4 g_w03[B_Q];
__device__ float4 g_w47[B_Q];
__device__ float4 g_w8b[B_Q];   // {w8, base(intbits), 0, 0}

// --------------------------------------------------- K1: per-query weights
__global__ __launch_bounds__(256) void k1_weights(
    const float* __restrict__ x,
    const float* __restrict__ ev,
    const float* __restrict__ tc,
    const int*   __restrict__ idx_tab,
    int nq)
{
    int q = blockIdx.x * blockDim.x + threadIdx.x;
    if (q >= nq) return;

    float xv = __ldg(&x[q]);

    // Uniform-grid guess (ev is linspace), exact +-2 argmin refine with
    // strict-< first-index tie-break (matches reference argmin).
    float e0 = __ldg(&ev[0]);
    float eN = __ldg(&ev[T_T - 1]);
    float inv_step = (float)(T_T - 1) / (eN - e0);
    int g = __float2int_rn((xv - e0) * inv_step);
    g = min(max(g, 0), T_T - 1);

    int lo = max(g - 2, 0), hi = min(g + 2, T_T - 1);
    int nidx = lo;
    float bd = 3.402823466e+38f;
    for (int j = lo; j <= hi; ++j) {
        float d = xv - __ldg(&ev[j]);
        d = d * d;
        if (d < bd) { bd = d; nidx = j; }
    }

    // takecare uses UNCLAMPED nearest idx; window uses clamped.
    float take = __ldg(&tc[nidx]);
    int idx_c = min(max(nidx, E_E), T_T - 1 - E_E);

    float lg[W_W];
    float m = -3.402823466e+38f;
    #pragma unroll
    for (int j = 0; j < W_W; ++j) {
        int w = idx_c + __ldg(&idx_tab[j]);
        float d = xv - __ldg(&ev[w]);
        float l = -(d * d) * take;
        lg[j] = l;
        m = fmaxf(m, l);
    }
    float ssum = 0.0f;
    #pragma unroll
    for (int j = 0; j < W_W; ++j) {
        float e = __expf(lg[j] - m);
        lg[j] = e;
        ssum += e;
    }
    float inv = __frcp_rn(ssum);

    g_w03[q] = make_float4(lg[0] * inv, lg[1] * inv, lg[2] * inv, lg[3] * inv);
    g_w47[q] = make_float4(lg[4] * inv, lg[5] * inv, lg[6] * inv, lg[7] * inv);
    g_w8b[q] = make_float4(lg[8] * inv, __int_as_float(idx_c), 0.f, 0.f);
}

// ----------------------------------------- K2: warp-per-query gather + FMA
__global__ __launch_bounds__(256) void k2_gather(
    const float* __restrict__ vec,
    float*       __restrict__ out,
    int nq)
{
    const int lane = threadIdx.x & 31;
    const int q = blockIdx.x * 8 + (threadIdx.x >> 5);
    if (q >= nq) return;

    // Uniform (warp-broadcast, one-line) weight loads.
    float4 w03 = __ldg(&g_w03[q]);
    float4 w47 = __ldg(&g_w47[q]);
    float4 w8b = __ldg(&g_w8b[q]);
    const int base = __float_as_int(w8b.y);

    const float wreg[W_W] = {w03.x, w03.y, w03.z, w03.w,
                             w47.x, w47.y, w47.z, w47.w, w8b.x};

    // Contiguous span: rows [base-4, base+4] = 576 floats, 18 aligned lines.
    // Element k*32 + lane -> row k>>1, col (k&1)*32 + lane.
    const float* wp = vec + (size_t)(base - E_E) * D_D;
    float acc0 = 0.0f, acc1 = 0.0f;
    #pragma unroll
    for (int k = 0; k < 18; ++k) {
        float v = __ldg(wp + k * 32 + lane);
        float wt = wreg[k >> 1];           // compile-time select (unrolled)
        if (k & 1) acc1 = fmaf(wt, v, acc1);
        else       acc0 = fmaf(wt, v, acc0);
    }

    float* op = out + (size_t)q * D_D;
    op[lane]      = acc0;
    op[32 + lane] = acc1;
}

extern "C" void kernel_launch(void* const* d_in, const int* in_sizes, int n_in,
                              void* d_out, int out_size)
{
    const float* x    = (const float*)d_in[0];
    const float* ev   = (const float*)d_in[1];
    const float* tc   = (const float*)d_in[2];
    const float* vec  = (const float*)d_in[3];
    const int*   itab = (const int*)d_in[4];
    float* out = (float*)d_out;

    int nq = in_sizes[0];

    k1_weights<<<(nq + 255) / 256, 256>>>(x, ev, tc, itab, nq);

    int grid2 = (nq + 7) / 8;          // 8 query-warps per 256-thread block
    k2_gather<<<grid2, 256>>>(vec, out, nq);
}